// round 6
// baseline (speedup 1.0000x reference)
#include <cuda_runtime.h>
#include <cuda_fp16.h>
#include <math.h>
#include <stdint.h>

#define NTOK   8192
#define DM     1024
#define HD     2048
#define NE     8
#define NRBLK  1024

// ---------------- scratch (static device globals; no allocation) ----------
__device__ int    g_cnt[NE];
__device__ int    g_list[NE * NTOK];                // packed tok*2+k
__device__ float  g_gate[NTOK * 2];
__device__ __half g_xh [(size_t)NTOK * DM];         // x in fp16
__device__ __half g_w1t[(size_t)NE * HD * DM];      // w1^T  [E][H][D] fp16
__device__ __half g_w2t[(size_t)NE * DM * HD];      // w2^T  [E][D][H] fp16
__device__ __half g_hid[(size_t)NTOK * 2 * HD];     // hidden fp16, by slot
__device__ float  g_outs[(size_t)NTOK * 2 * DM];    // expert outs fp32, by slot
__device__ float  g_part[NRBLK * 10];

// ---------------- PTX helpers ----------------------------------------------
static __device__ __forceinline__ uint32_t smem_u32(const void* p) {
    uint32_t a;
    asm("{ .reg .u64 t; cvta.to.shared.u64 t, %1; cvt.u32.u64 %0, t; }" : "=r"(a) : "l"(p));
    return a;
}
#define CP_ASYNC16(dst, src, sz) \
    asm volatile("cp.async.cg.shared.global [%0], [%1], 16, %2;" \
        :: "r"(dst), "l"(src), "r"(sz))
#define CP_COMMIT() asm volatile("cp.async.commit_group;")
#define CP_WAIT(N)  asm volatile("cp.async.wait_group %0;" :: "n"(N))

#define LDSM_X4(r0, r1, r2, r3, a) \
    asm volatile("ldmatrix.sync.aligned.m8n8.x4.shared.b16 {%0,%1,%2,%3}, [%4];" \
        : "=r"(r0), "=r"(r1), "=r"(r2), "=r"(r3) : "r"(a))

#define MMA16816(d, a, b) \
    asm volatile("mma.sync.aligned.m16n8k16.row.col.f32.f16.f16.f32 " \
        "{%0,%1,%2,%3}, {%4,%5,%6,%7}, {%8,%9}, {%0,%1,%2,%3};" \
        : "+f"((d)[0]), "+f"((d)[1]), "+f"((d)[2]), "+f"((d)[3]) \
        : "r"((a)[0]), "r"((a)[1]), "r"((a)[2]), "r"((a)[3]), "r"((b)[0]), "r"((b)[1]))

// ---------------- init -----------------------------------------------------
__global__ void zero_kernel() {
    if (threadIdx.x < NE) g_cnt[threadIdx.x] = 0;
}

// ---------------- pre-pass: x -> fp16 ---------------------------------------
__global__ void convx_kernel(const float* __restrict__ x) {
    size_t i = ((size_t)blockIdx.x * 256 + threadIdx.x) * 8;
    float4 a = *(const float4*)(x + i);
    float4 b = *(const float4*)(x + i + 4);
    __half h[8];
    h[0] = __float2half_rn(a.x); h[1] = __float2half_rn(a.y);
    h[2] = __float2half_rn(a.z); h[3] = __float2half_rn(a.w);
    h[4] = __float2half_rn(b.x); h[5] = __float2half_rn(b.y);
    h[6] = __float2half_rn(b.z); h[7] = __float2half_rn(b.w);
    *(uint4*)(g_xh + i) = *(uint4*)h;
}

// ---------------- pre-pass: transpose + convert weights ---------------------
// W [E][R][C] fp32 -> Wt [E][C][R] fp16.  256 threads, 32x32 tile,
// vectorized 8B fp16 writes (4 halves/thread).
template<bool FIRST>
__global__ void transp_kernel(const float* __restrict__ W, int R, int C) {
    __shared__ float t[32][33];
    int c0 = blockIdx.x * 32, r0 = blockIdx.y * 32, e = blockIdx.z;
    int tid = threadIdx.x;
    int tx = tid & 31, ty = tid >> 5;
    const float* src = W + (size_t)e * R * C;
    __half* dst = (FIRST ? g_w1t : g_w2t) + (size_t)e * R * C;
#pragma unroll
    for (int i = 0; i < 4; i++)
        t[ty + 8 * i][tx] = src[(size_t)(r0 + ty + 8 * i) * C + c0 + tx];
    __syncthreads();
    int row = tid >> 3;     // local col index (0..31)
    int seg = tid & 7;      // 4 halves per thread
    __half h4[4];
#pragma unroll
    for (int j = 0; j < 4; j++)
        h4[j] = __float2half_rn(t[seg * 4 + j][row]);
    *(uint2*)(dst + (size_t)(c0 + row) * R + r0 + seg * 4) = *(uint2*)h4;
}

// ---------------- router: one warp per token --------------------------------
__global__ void router_kernel(const float* __restrict__ x,
                              const float* __restrict__ rw,
                              const float* __restrict__ rb) {
    int warp = threadIdx.x >> 5;
    int lane = threadIdx.x & 31;
    int tok  = blockIdx.x * 8 + warp;

    __shared__ float s_probs[8][NE];
    __shared__ float s_z2[8];
    __shared__ float s_ent[8];

    float acc[NE];
#pragma unroll
    for (int e = 0; e < NE; e++) acc[e] = 0.f;

    const float* h = x + (size_t)tok * DM;
    for (int d = lane; d < DM; d += 32) {
        float hv = h[d];
        const float* wrow = rw + d * NE;
#pragma unroll
        for (int e = 0; e < NE; e++) acc[e] += hv * wrow[e];
    }
#pragma unroll
    for (int e = 0; e < NE; e++) {
#pragma unroll
        for (int o = 16; o > 0; o >>= 1)
            acc[e] += __shfl_xor_sync(0xffffffffu, acc[e], o);
    }

    if (lane == 0) {
        float logit[NE];
        float mx = -1e30f;
#pragma unroll
        for (int e = 0; e < NE; e++) { logit[e] = acc[e] + rb[e]; mx = fmaxf(mx, logit[e]); }
        float p[NE];
        float s = 0.f;
#pragma unroll
        for (int e = 0; e < NE; e++) { p[e] = expf(logit[e] - mx); s += p[e]; }
        float inv = 1.f / s;
        float ent = 0.f;
#pragma unroll
        for (int e = 0; e < NE; e++) { p[e] *= inv; ent -= p[e] * logf(p[e] + 1e-10f); }
        float z = mx + logf(s);

        int i1 = 0;
#pragma unroll
        for (int e = 1; e < NE; e++) if (p[e] > p[i1]) i1 = e;
        int i2 = -1;
#pragma unroll
        for (int e = 0; e < NE; e++) {
            if (e == i1) continue;
            if (i2 < 0 || p[e] > p[i2]) i2 = e;
        }
        float wsum = p[i1] + p[i2] + 1e-9f;
        g_gate[tok * 2 + 0] = p[i1] / wsum;
        g_gate[tok * 2 + 1] = p[i2] / wsum;

        int pos1 = atomicAdd(&g_cnt[i1], 1);
        g_list[i1 * NTOK + pos1] = tok * 2 + 0;
        int pos2 = atomicAdd(&g_cnt[i2], 1);
        g_list[i2 * NTOK + pos2] = tok * 2 + 1;

#pragma unroll
        for (int e = 0; e < NE; e++) s_probs[warp][e] = p[e];
        s_z2[warp]  = z * z;
        s_ent[warp] = ent;
    }
    __syncthreads();
    if (threadIdx.x == 0) {
        float* pp = &g_part[blockIdx.x * 10];
        for (int e = 0; e < NE; e++) {
            float t = 0.f;
            for (int w = 0; w < 8; w++) t += s_probs[w][e];
            pp[e] = t;
        }
        float tz = 0.f, te = 0.f;
        for (int w = 0; w < 8; w++) { tz += s_z2[w]; te += s_ent[w]; }
        pp[8] = tz; pp[9] = te;
    }
}

// ---------------- scalar reduce (fixed order => deterministic) --------------
__global__ void reduce_kernel(float* __restrict__ out_tail) {
    __shared__ float comp[10];
    int t = threadIdx.x;
    if (t < 10) {
        float s = 0.f;
        for (int b = 0; b < NRBLK; b++) s += g_part[b * 10 + t];
        comp[t] = s;
    }
    __syncthreads();
    if (t == 0) {
        float lb = 0.f;
        float Pe[NE], fe[NE];
        for (int e = 0; e < NE; e++) {
            Pe[e] = comp[e] / (float)NTOK;
            fe[e] = (float)g_cnt[e] / (float)NTOK;
            lb += fe[e] * Pe[e];
        }
        out_tail[0] = -(float)NE * lb;
        out_tail[1] = comp[8] / (float)NTOK;
        out_tail[2] = comp[9] / (float)NTOK;
        for (int e = 0; e < NE; e++) out_tail[3 + e]  = fe[e];
        for (int e = 0; e < NE; e++) out_tail[11 + e] = Pe[e];
    }
}

// ---------------- HMMA gather GEMM ------------------------------------------
// C[256 gathered rows, 128 cols at n0] = A[*, KD] @ B[e][n0+*][KD]^T
// 512 threads = 16 warps (8 M x 2 N), warp tile 32x64.
// 4-stage cp.async pipeline, one __syncthreads per K-chunk.
// smem rows padded to 40 halfs (80B): conflict-free ldmatrix.
#define ROWH 40
#define MT 256
#define A_TILE_B (MT * ROWH * 2)          // 20480 bytes
#define B_TILE_B (128 * ROWH * 2)         // 10240 bytes
#define STAGE_B (A_TILE_B + B_TILE_B)     // 30720
#define NSTAGE 4
#define GSMEM (NSTAGE * STAGE_B)          // 122880

template<int KD, int NTOT, bool IS1>
__global__ __launch_bounds__(512, 1)
void gemm_hmma(const __half* __restrict__ Ain, const __half* __restrict__ Bw,
               const float* __restrict__ bias) {
    const int e    = blockIdx.z;
    const int cnt  = g_cnt[e];
    const int row0 = blockIdx.y * MT;
    if (row0 >= cnt) return;
    const int n0   = blockIdx.x * 128;

    extern __shared__ __align__(16) char dynsm[];
    __shared__ int s_row[MT];

    const int tid  = threadIdx.x;
    const int wid  = tid >> 5;
    const int lane = tid & 31;

    if (tid < MT) {
        int r = row0 + tid;
        s_row[tid] = (r < cnt) ? g_list[e * NTOK + r] : -1;
    }
    __syncthreads();

    const uint32_t base = smem_u32(dynsm);
    const __half* Brow = Bw + ((size_t)e * NTOT + n0) * KD;

    // loader: chunk kc -> stage s.  A: 1024 x 16B, B: 512 x 16B, 3 per thread.
    auto load_chunk = [&](int kc, int s) {
        const uint32_t ab = base + s * STAGE_B;
        const uint32_t bb = ab + A_TILE_B;
#pragma unroll
        for (int it = 0; it < 2; it++) {
            int idx  = tid + it * 512;           // 0..1023
            int unit = idx & 3;
            int r    = idx >> 2;                 // 0..255
            uint32_t soff = (uint32_t)(r * (ROWH * 2) + unit * 16);
            int packed = s_row[r];
            const __half* asrc = Ain;
            int sz = 0;
            if (packed >= 0) {
                int arow = IS1 ? (packed >> 1) : packed;
                asrc = Ain + (size_t)arow * KD + kc * 32 + unit * 8;
                sz = 16;
            }
            CP_ASYNC16(ab + soff, asrc, sz);
        }
        {
            int unit = tid & 3;
            int r    = tid >> 2;                 // 0..127
            uint32_t soff = (uint32_t)(r * (ROWH * 2) + unit * 16);
            const __half* bsrc = Brow + (size_t)r * KD + kc * 32 + unit * 8;
            CP_ASYNC16(bb + soff, bsrc, 16);
        }
        CP_COMMIT();
    };

    float acc[2][8][4];
#pragma unroll
    for (int i = 0; i < 2; i++)
#pragma unroll
        for (int j = 0; j < 8; j++)
#pragma unroll
            for (int q = 0; q < 4; q++) acc[i][j][q] = 0.f;

    const int m_base = (wid & 7) * 32;
    const int n_base = (wid >> 3) * 64;
    const int group  = lane >> 3;
    const int rloc   = lane & 7;

    const int NKC = KD / 32;
    load_chunk(0, 0);
    load_chunk(1, 1);
    load_chunk(2, 2);

    for (int kc = 0; kc < NKC; kc++) {
        CP_WAIT(2);                     // groups <= kc complete
        __syncthreads();
        if (kc + 3 < NKC) load_chunk(kc + 3, (kc + 3) & 3);

        const uint32_t ab = base + (kc & 3) * STAGE_B;
        const uint32_t bb = ab + A_TILE_B;
#pragma unroll
        for (int k16 = 0; k16 < 2; k16++) {
            uint32_t a[2][4], b[4][4];
#pragma unroll
            for (int mi = 0; mi < 2; mi++) {
                int row  = m_base + 16 * mi + rloc + (group & 1) * 8;
                int koff = k16 * 16 + (group >> 1) * 8;
                LDSM_X4(a[mi][0], a[mi][1], a[mi][2], a[mi][3],
                        ab + row * (ROWH * 2) + koff * 2);
            }
#pragma unroll
            for (int nb = 0; nb < 4; nb++) {
                int row  = n_base + 16 * nb + rloc + (group >> 1) * 8;
                int koff = k16 * 16 + (group & 1) * 8;
                LDSM_X4(b[nb][0], b[nb][1], b[nb][2], b[nb][3],
                        bb + row * (ROWH * 2) + koff * 2);
            }
#pragma unroll
            for (int mi = 0; mi < 2; mi++)
#pragma unroll
                for (int nj = 0; nj < 8; nj++) {
                    uint32_t bf[2] = { b[nj >> 1][(nj & 1) * 2],
                                       b[nj >> 1][(nj & 1) * 2 + 1] };
                    MMA16816(acc[mi][nj], a[mi], bf);
                }
        }
    }

    // epilogue
    const int crow = lane >> 2;
    const int ccol = (lane & 3) * 2;
#pragma unroll
    for (int mi = 0; mi < 2; mi++) {
#pragma unroll
        for (int half_m = 0; half_m < 2; half_m++) {
            int r = m_base + 16 * mi + crow + half_m * 8;
            int packed = s_row[r];
            if (packed < 0) continue;
#pragma unroll
            for (int nj = 0; nj < 8; nj++) {
                int gc = n0 + n_base + 8 * nj + ccol;
                float v0 = acc[mi][nj][half_m * 2 + 0] + bias[(size_t)e * NTOT + gc];
                float v1 = acc[mi][nj][half_m * 2 + 1] + bias[(size_t)e * NTOT + gc + 1];
                if (IS1) {
                    v0 = 0.5f * v0 * (1.0f + erff(v0 * 0.70710678118654752f));
                    v1 = 0.5f * v1 * (1.0f + erff(v1 * 0.70710678118654752f));
                    __half2 h = __floats2half2_rn(v0, v1);
                    *(__half2*)(g_hid + (size_t)packed * HD + gc) = h;
                } else {
                    float2 f = make_float2(v0, v1);
                    *(float2*)(g_outs + (size_t)packed * DM + gc) = f;
                }
            }
        }
    }
}

// ---------------- combine: y = g1*out_slot0 + g2*out_slot1 ------------------
__global__ void combine_kernel(float* __restrict__ y) {
    int i = blockIdx.x * 256 + threadIdx.x;
    int n = i >> 10;
    int d = i & 1023;
    float g0 = g_gate[2 * n + 0];
    float g1 = g_gate[2 * n + 1];
    y[i] = g0 * g_outs[(size_t)(2 * n + 0) * DM + d]
         + g1 * g_outs[(size_t)(2 * n + 1) * DM + d];
}

// ---------------- launch -----------------------------------------------------
extern "C" void kernel_launch(void* const* d_in, const int* in_sizes, int n_in,
                              void* d_out, int out_size) {
    const float* x  = (const float*)d_in[0];
    const float* rw = (const float*)d_in[1];
    const float* rb = (const float*)d_in[2];
    const float* w1 = (const float*)d_in[3];
    const float* b1 = (const float*)d_in[4];
    const float* w2 = (const float*)d_in[5];
    const float* b2 = (const float*)d_in[6];
    float* out = (float*)d_out;

    __half* xh  = nullptr; cudaGetSymbolAddress((void**)&xh,  g_xh);
    __half* w1t = nullptr; cudaGetSymbolAddress((void**)&w1t, g_w1t);
    __half* w2t = nullptr; cudaGetSymbolAddress((void**)&w2t, g_w2t);
    __half* hid = nullptr; cudaGetSymbolAddress((void**)&hid, g_hid);

    cudaFuncSetAttribute(gemm_hmma<DM, HD, true>,
                         cudaFuncAttributeMaxDynamicSharedMemorySize, GSMEM);
    cudaFuncSetAttribute(gemm_hmma<HD, DM, false>,
                         cudaFuncAttributeMaxDynamicSharedMemorySize, GSMEM);

    zero_kernel<<<1, 32>>>();
    router_kernel<<<NRBLK, 256>>>(x, rw, rb);
    reduce_kernel<<<1, 32>>>(out + (size_t)NTOK * DM);

    convx_kernel<<<(NTOK * DM) / (256 * 8), 256>>>(x);
    {
        dim3 gt1(HD / 32, DM / 32, NE);
        transp_kernel<true><<<gt1, 256>>>(w1, DM, HD);
        dim3 gt2(DM / 32, HD / 32, NE);
        transp_kernel<false><<<gt2, 256>>>(w2, HD, DM);
    }

    {
        dim3 gg1(HD / 128, NTOK / MT, NE);
        gemm_hmma<DM, HD, true><<<gg1, 512, GSMEM>>>(xh, w1t, b1);
        dim3 gg2(DM / 128, NTOK / MT, NE);
        gemm_hmma<HD, DM, false><<<gg2, 512, GSMEM>>>(hid, w2t, b2);
    }

    combine_kernel<<<(NTOK * DM) / 256, 256>>>(out);
}

// round 7
// speedup vs baseline: 1.2871x; 1.2871x over previous
#include <cuda_runtime.h>
#include <cuda_fp16.h>
#include <math.h>
#include <stdint.h>

#define NTOK   8192
#define DM     1024
#define HD     2048
#define NE     8
#define NRBLK  1024

// ---------------- scratch (static device globals; no allocation) ----------
__device__ int    g_cnt[NE];
__device__ int    g_list[NE * NTOK];                // packed tok*2+k
__device__ float  g_gate[NTOK * 2];
__device__ __half g_xh [(size_t)NTOK * DM];         // x in fp16
__device__ __half g_w1t[(size_t)NE * HD * DM];      // w1^T  [E][H][D] fp16
__device__ __half g_w2t[(size_t)NE * DM * HD];      // w2^T  [E][D][H] fp16
__device__ __half g_hid[(size_t)NTOK * 2 * HD];     // hidden fp16, by slot
__device__ float  g_outs[(size_t)NTOK * 2 * DM];    // expert outs fp32, by slot
__device__ float  g_part[NRBLK * 10];

// ---------------- PTX helpers ----------------------------------------------
static __device__ __forceinline__ uint32_t smem_u32(const void* p) {
    uint32_t a;
    asm("{ .reg .u64 t; cvta.to.shared.u64 t, %1; cvt.u32.u64 %0, t; }" : "=r"(a) : "l"(p));
    return a;
}
#define CP_ASYNC16(dst, src, sz) \
    asm volatile("cp.async.cg.shared.global [%0], [%1], 16, %2;" \
        :: "r"(dst), "l"(src), "r"(sz))
#define CP_COMMIT() asm volatile("cp.async.commit_group;")
#define CP_WAIT(N)  asm volatile("cp.async.wait_group %0;" :: "n"(N))

#define LDSM_X4(r0, r1, r2, r3, a) \
    asm volatile("ldmatrix.sync.aligned.m8n8.x4.shared.b16 {%0,%1,%2,%3}, [%4];" \
        : "=r"(r0), "=r"(r1), "=r"(r2), "=r"(r3) : "r"(a))

#define MMA16816(d, a, b) \
    asm volatile("mma.sync.aligned.m16n8k16.row.col.f32.f16.f16.f32 " \
        "{%0,%1,%2,%3}, {%4,%5,%6,%7}, {%8,%9}, {%0,%1,%2,%3};" \
        : "+f"((d)[0]), "+f"((d)[1]), "+f"((d)[2]), "+f"((d)[3]) \
        : "r"((a)[0]), "r"((a)[1]), "r"((a)[2]), "r"((a)[3]), "r"((b)[0]), "r"((b)[1]))

// ---------------- init -----------------------------------------------------
__global__ void zero_kernel() {
    if (threadIdx.x < NE) g_cnt[threadIdx.x] = 0;
}

// ---------------- pre-pass: x -> fp16 ---------------------------------------
__global__ void convx_kernel(const float* __restrict__ x) {
    size_t i = ((size_t)blockIdx.x * 256 + threadIdx.x) * 8;
    float4 a = *(const float4*)(x + i);
    float4 b = *(const float4*)(x + i + 4);
    __half h[8];
    h[0] = __float2half_rn(a.x); h[1] = __float2half_rn(a.y);
    h[2] = __float2half_rn(a.z); h[3] = __float2half_rn(a.w);
    h[4] = __float2half_rn(b.x); h[5] = __float2half_rn(b.y);
    h[6] = __float2half_rn(b.z); h[7] = __float2half_rn(b.w);
    *(uint4*)(g_xh + i) = *(uint4*)h;
}

// ---------------- pre-pass: transpose + convert weights ---------------------
// W [E][R][C] fp32 -> Wt [E][C][R] fp16.  256 threads, 32x32 tile,
// vectorized 8B fp16 writes (4 halves/thread).
template<bool FIRST>
__global__ void transp_kernel(const float* __restrict__ W, int R, int C) {
    __shared__ float t[32][33];
    int c0 = blockIdx.x * 32, r0 = blockIdx.y * 32, e = blockIdx.z;
    int tid = threadIdx.x;
    int tx = tid & 31, ty = tid >> 5;
    const float* src = W + (size_t)e * R * C;
    __half* dst = (FIRST ? g_w1t : g_w2t) + (size_t)e * R * C;
#pragma unroll
    for (int i = 0; i < 4; i++)
        t[ty + 8 * i][tx] = src[(size_t)(r0 + ty + 8 * i) * C + c0 + tx];
    __syncthreads();
    int row = tid >> 3;     // local col index (0..31)
    int seg = tid & 7;      // 4 halves per thread
    __half h4[4];
#pragma unroll
    for (int j = 0; j < 4; j++)
        h4[j] = __float2half_rn(t[seg * 4 + j][row]);
    *(uint2*)(dst + (size_t)(c0 + row) * R + r0 + seg * 4) = *(uint2*)h4;
}

// ---------------- router: one warp per token --------------------------------
__global__ void router_kernel(const float* __restrict__ x,
                              const float* __restrict__ rw,
                              const float* __restrict__ rb) {
    int warp = threadIdx.x >> 5;
    int lane = threadIdx.x & 31;
    int tok  = blockIdx.x * 8 + warp;

    __shared__ float s_probs[8][NE];
    __shared__ float s_z2[8];
    __shared__ float s_ent[8];

    float acc[NE];
#pragma unroll
    for (int e = 0; e < NE; e++) acc[e] = 0.f;

    const float* h = x + (size_t)tok * DM;
    for (int d = lane; d < DM; d += 32) {
        float hv = h[d];
        const float* wrow = rw + d * NE;
#pragma unroll
        for (int e = 0; e < NE; e++) acc[e] += hv * wrow[e];
    }
#pragma unroll
    for (int e = 0; e < NE; e++) {
#pragma unroll
        for (int o = 16; o > 0; o >>= 1)
            acc[e] += __shfl_xor_sync(0xffffffffu, acc[e], o);
    }

    if (lane == 0) {
        float logit[NE];
        float mx = -1e30f;
#pragma unroll
        for (int e = 0; e < NE; e++) { logit[e] = acc[e] + rb[e]; mx = fmaxf(mx, logit[e]); }
        float p[NE];
        float s = 0.f;
#pragma unroll
        for (int e = 0; e < NE; e++) { p[e] = expf(logit[e] - mx); s += p[e]; }
        float inv = 1.f / s;
        float ent = 0.f;
#pragma unroll
        for (int e = 0; e < NE; e++) { p[e] *= inv; ent -= p[e] * logf(p[e] + 1e-10f); }
        float z = mx + logf(s);

        int i1 = 0;
#pragma unroll
        for (int e = 1; e < NE; e++) if (p[e] > p[i1]) i1 = e;
        int i2 = -1;
#pragma unroll
        for (int e = 0; e < NE; e++) {
            if (e == i1) continue;
            if (i2 < 0 || p[e] > p[i2]) i2 = e;
        }
        float wsum = p[i1] + p[i2] + 1e-9f;
        g_gate[tok * 2 + 0] = p[i1] / wsum;
        g_gate[tok * 2 + 1] = p[i2] / wsum;

        int pos1 = atomicAdd(&g_cnt[i1], 1);
        g_list[i1 * NTOK + pos1] = tok * 2 + 0;
        int pos2 = atomicAdd(&g_cnt[i2], 1);
        g_list[i2 * NTOK + pos2] = tok * 2 + 1;

#pragma unroll
        for (int e = 0; e < NE; e++) s_probs[warp][e] = p[e];
        s_z2[warp]  = z * z;
        s_ent[warp] = ent;
    }
    __syncthreads();
    if (threadIdx.x == 0) {
        float* pp = &g_part[blockIdx.x * 10];
        for (int e = 0; e < NE; e++) {
            float t = 0.f;
            for (int w = 0; w < 8; w++) t += s_probs[w][e];
            pp[e] = t;
        }
        float tz = 0.f, te = 0.f;
        for (int w = 0; w < 8; w++) { tz += s_z2[w]; te += s_ent[w]; }
        pp[8] = tz; pp[9] = te;
    }
}

// ---------------- scalar reduce (fixed order => deterministic) --------------
__global__ void reduce_kernel(float* __restrict__ out_tail) {
    __shared__ float comp[10];
    int t = threadIdx.x;
    if (t < 10) {
        float s = 0.f;
        for (int b = 0; b < NRBLK; b++) s += g_part[b * 10 + t];
        comp[t] = s;
    }
    __syncthreads();
    if (t == 0) {
        float lb = 0.f;
        float Pe[NE], fe[NE];
        for (int e = 0; e < NE; e++) {
            Pe[e] = comp[e] / (float)NTOK;
            fe[e] = (float)g_cnt[e] / (float)NTOK;
            lb += fe[e] * Pe[e];
        }
        out_tail[0] = -(float)NE * lb;
        out_tail[1] = comp[8] / (float)NTOK;
        out_tail[2] = comp[9] / (float)NTOK;
        for (int e = 0; e < NE; e++) out_tail[3 + e]  = fe[e];
        for (int e = 0; e < NE; e++) out_tail[11 + e] = Pe[e];
    }
}

// ---------------- HMMA gather GEMM ------------------------------------------
// C[128 gathered rows, 128 cols at n0] = A[*, KD] @ B[e][n0+*][KD]^T
// 256 threads = 8 warps (2 M x 4 N), warp tile 64x32.  K-chunk = 64.
// 3-stage cp.async pipeline, one __syncthreads per chunk, exact tail waits.
// smem rows padded to 72 halfs (144B): conflict-free ldmatrix + stores.
#define ROWH 72
#define TILE_B (128 * ROWH * 2)           // 18432 bytes per matrix per stage
#define STAGE_B (2 * TILE_B)              // 36864: A then B
#define GSMEM (3 * STAGE_B)               // 110592

template<int KD, int NTOT, bool IS1>
__global__ __launch_bounds__(256, 2)
void gemm_hmma(const __half* __restrict__ Ain, const __half* __restrict__ Bw,
               const float* __restrict__ bias) {
    const int e    = blockIdx.z;
    const int cnt  = g_cnt[e];
    const int row0 = blockIdx.y * 128;
    if (row0 >= cnt) return;
    const int n0   = blockIdx.x * 128;

    extern __shared__ __align__(16) char dynsm[];
    __shared__ int s_row[128];

    const int tid  = threadIdx.x;
    const int wid  = tid >> 5;
    const int lane = tid & 31;

    if (tid < 128) {
        int r = row0 + tid;
        s_row[tid] = (r < cnt) ? g_list[e * NTOK + r] : -1;
    }
    __syncthreads();

    const uint32_t base = smem_u32(dynsm);
    const __half* Brow = Bw + ((size_t)e * NTOT + n0) * KD;

    // loader: 64-wide K chunk kc -> stage s.  A,B each 1024 x 16B units.
    auto load_chunk = [&](int kc, int s) {
        const uint32_t ab = base + s * STAGE_B;
        const uint32_t bb = ab + TILE_B;
#pragma unroll
        for (int it = 0; it < 4; it++) {
            int idx  = tid + it * 256;           // 0..1023
            int unit = idx & 7;                  // 8 x 16B per 128B row
            int r    = idx >> 3;                 // 0..127
            uint32_t soff = (uint32_t)(r * (ROWH * 2) + unit * 16);
            int packed = s_row[r];
            const __half* asrc = Ain;
            int sz = 0;
            if (packed >= 0) {
                int arow = IS1 ? (packed >> 1) : packed;
                asrc = Ain + (size_t)arow * KD + kc * 64 + unit * 8;
                sz = 16;
            }
            CP_ASYNC16(ab + soff, asrc, sz);
            const __half* bsrc = Brow + (size_t)r * KD + kc * 64 + unit * 8;
            CP_ASYNC16(bb + soff, bsrc, 16);
        }
        CP_COMMIT();
    };

    float acc[4][4][4];
#pragma unroll
    for (int i = 0; i < 4; i++)
#pragma unroll
        for (int j = 0; j < 4; j++)
#pragma unroll
            for (int q = 0; q < 4; q++) acc[i][j][q] = 0.f;

    const int m_base = (wid & 1) * 64;
    const int n_base = (wid >> 1) * 32;
    const int group  = lane >> 3;
    const int rloc   = lane & 7;

    const int NKC = KD / 64;
    load_chunk(0, 0);
    load_chunk(1, 1);

    int st = 2;                     // stage to fill next (rotates 0,1,2)
    for (int kc = 0; kc < NKC; kc++) {
        CP_WAIT(1);                 // exactly: all but latest group done => kc done
        __syncthreads();
        if (kc + 2 < NKC) {
            load_chunk(kc + 2, st);
        } else {
            CP_COMMIT();            // empty group keeps wait(1) exact at tail
        }

        const int cur = (st + 1 == 3) ? 0 : st + 1;   // == kc % 3
        st = cur;
        const uint32_t ab = base + ((kc % 3)) * STAGE_B;
        const uint32_t bb = ab + TILE_B;
#pragma unroll
        for (int k16 = 0; k16 < 4; k16++) {
            uint32_t a[4][4], b[2][4];
#pragma unroll
            for (int mi = 0; mi < 4; mi++) {
                int row  = m_base + 16 * mi + rloc + (group & 1) * 8;
                int koff = k16 * 16 + (group >> 1) * 8;
                LDSM_X4(a[mi][0], a[mi][1], a[mi][2], a[mi][3],
                        ab + row * (ROWH * 2) + koff * 2);
            }
#pragma unroll
            for (int nb = 0; nb < 2; nb++) {
                int row  = n_base + 16 * nb + rloc + (group >> 1) * 8;
                int koff = k16 * 16 + (group & 1) * 8;
                LDSM_X4(b[nb][0], b[nb][1], b[nb][2], b[nb][3],
                        bb + row * (ROWH * 2) + koff * 2);
            }
#pragma unroll
            for (int mi = 0; mi < 4; mi++)
#pragma unroll
                for (int nj = 0; nj < 4; nj++) {
                    uint32_t bf[2] = { b[nj >> 1][(nj & 1) * 2],
                                       b[nj >> 1][(nj & 1) * 2 + 1] };
                    MMA16816(acc[mi][nj], a[mi], bf);
                }
        }
    }

    // epilogue
    const int crow = lane >> 2;
    const int ccol = (lane & 3) * 2;
#pragma unroll
    for (int mi = 0; mi < 4; mi++) {
#pragma unroll
        for (int half_m = 0; half_m < 2; half_m++) {
            int r = m_base + 16 * mi + crow + half_m * 8;
            int packed = s_row[r];
            if (packed < 0) continue;
#pragma unroll
            for (int nj = 0; nj < 4; nj++) {
                int gc = n0 + n_base + 8 * nj + ccol;
                float v0 = acc[mi][nj][half_m * 2 + 0] + bias[(size_t)e * NTOT + gc];
                float v1 = acc[mi][nj][half_m * 2 + 1] + bias[(size_t)e * NTOT + gc + 1];
                if (IS1) {
                    v0 = 0.5f * v0 * (1.0f + erff(v0 * 0.70710678118654752f));
                    v1 = 0.5f * v1 * (1.0f + erff(v1 * 0.70710678118654752f));
                    __half2 h = __floats2half2_rn(v0, v1);
                    *(__half2*)(g_hid + (size_t)packed * HD + gc) = h;
                } else {
                    float2 f = make_float2(v0, v1);
                    *(float2*)(g_outs + (size_t)packed * DM + gc) = f;
                }
            }
        }
    }
}

// ---------------- combine: y = g1*out_slot0 + g2*out_slot1 ------------------
__global__ void combine_kernel(float* __restrict__ y) {
    int i = blockIdx.x * 256 + threadIdx.x;
    int n = i >> 10;
    int d = i & 1023;
    float g0 = g_gate[2 * n + 0];
    float g1 = g_gate[2 * n + 1];
    y[i] = g0 * g_outs[(size_t)(2 * n + 0) * DM + d]
         + g1 * g_outs[(size_t)(2 * n + 1) * DM + d];
}

// ---------------- launch -----------------------------------------------------
extern "C" void kernel_launch(void* const* d_in, const int* in_sizes, int n_in,
                              void* d_out, int out_size) {
    const float* x  = (const float*)d_in[0];
    const float* rw = (const float*)d_in[1];
    const float* rb = (const float*)d_in[2];
    const float* w1 = (const float*)d_in[3];
    const float* b1 = (const float*)d_in[4];
    const float* w2 = (const float*)d_in[5];
    const float* b2 = (const float*)d_in[6];
    float* out = (float*)d_out;

    __half* xh  = nullptr; cudaGetSymbolAddress((void**)&xh,  g_xh);
    __half* w1t = nullptr; cudaGetSymbolAddress((void**)&w1t, g_w1t);
    __half* w2t = nullptr; cudaGetSymbolAddress((void**)&w2t, g_w2t);
    __half* hid = nullptr; cudaGetSymbolAddress((void**)&hid, g_hid);

    cudaFuncSetAttribute(gemm_hmma<DM, HD, true>,
                         cudaFuncAttributeMaxDynamicSharedMemorySize, GSMEM);
    cudaFuncSetAttribute(gemm_hmma<HD, DM, false>,
                         cudaFuncAttributeMaxDynamicSharedMemorySize, GSMEM);

    zero_kernel<<<1, 32>>>();
    router_kernel<<<NRBLK, 256>>>(x, rw, rb);
    reduce_kernel<<<1, 32>>>(out + (size_t)NTOK * DM);

    convx_kernel<<<(NTOK * DM) / (256 * 8), 256>>>(x);
    {
        dim3 gt1(HD / 32, DM / 32, NE);
        transp_kernel<true><<<gt1, 256>>>(w1, DM, HD);
        dim3 gt2(DM / 32, HD / 32, NE);
        transp_kernel<false><<<gt2, 256>>>(w2, HD, DM);
    }

    {
        dim3 gg1(HD / 128, NTOK / 128, NE);
        gemm_hmma<DM, HD, true><<<gg1, 256, GSMEM>>>(xh, w1t, b1);
        dim3 gg2(DM / 128, NTOK / 128, NE);
        gemm_hmma<HD, DM, false><<<gg2, 256, GSMEM>>>(hid, w2t, b2);
    }

    combine_kernel<<<(NTOK * DM) / 256, 256>>>(out);
}